// round 3
// baseline (speedup 1.0000x reference)
#include <cuda_runtime.h>
#include <math.h>

// Problem constants
#define BB 4
#define SS 2048
#define CC 1024
#define HH 4
#define MROWS (BB*SS)        // 8192 rows of activations
#define C3 (3*CC)            // 3072

// ---------------------------------------------------------------------------
// Scratch (static device globals; no runtime allocation)
// ---------------------------------------------------------------------------
__device__ float g_h   [MROWS*(long)CC];   // 32 MB  current hidden
__device__ float g_tmp [MROWS*(long)CC];   // 32 MB  gemm temp
__device__ float g_pred[MROWS*(long)CC];   // 32 MB  first-layer output (residual)
__device__ float g_att [MROWS*(long)CC];   // 32 MB  attention output
__device__ float g_qkv [MROWS*(long)C3];   // 96 MB  fused qkv
__device__ float g_kv  [BB*(long)CC*CC];   // 16 MB  per-batch k^T v

// ---------------------------------------------------------------------------
// SGEMM: C = alpha * op(A) @ op(B) + bias
//   AM==0: A[m,k] = A[m*lda+k]   AM==1: A[m,k] = A[k*lda+m]
//   BM==0: B[k,n] = B[k*ldb+n]   BM==1: B[k,n] = B[n*ldb+k]
// 128x128 block tile, KTILE=8, 256 threads, 8x8 per-thread microtile.
// All dims here are multiples of tile sizes (M,N %128==0, K%8==0) — no guards.
// ---------------------------------------------------------------------------
#define TILE 128
#define KTILE 8

template<int AM, int BM>
__global__ void __launch_bounds__(256)
sgemm(const float* __restrict__ Ag, const float* __restrict__ Bg,
      const float* __restrict__ bias, float* __restrict__ Cg,
      int M, int N, int K, int lda, int ldb, int ldc,
      long sA, long sB, long sC, float alpha)
{
    const float* A = Ag + (long)blockIdx.z * sA;
    const float* B = Bg + (long)blockIdx.z * sB;
    float*       C = Cg + (long)blockIdx.z * sC;

    __shared__ float As[KTILE][TILE];
    __shared__ float Bs[KTILE][TILE];

    const int tid = threadIdx.x;
    const int m0 = blockIdx.y * TILE;
    const int n0 = blockIdx.x * TILE;
    const int tx = tid & 15;   // 0..15 -> column group
    const int ty = tid >> 4;   // 0..15 -> row group

    float acc[8][8];
    #pragma unroll
    for (int i = 0; i < 8; i++)
        #pragma unroll
        for (int j = 0; j < 8; j++) acc[i][j] = 0.f;

    for (int k0 = 0; k0 < K; k0 += KTILE) {
        // ---- load A tile -> As[k][m] ----
        if (AM == 0) {
            int m  = tid >> 1;
            int kk = (tid & 1) * 4;
            float4 va = *(const float4*)(A + (long)(m0 + m) * lda + k0 + kk);
            As[kk+0][m] = va.x; As[kk+1][m] = va.y;
            As[kk+2][m] = va.z; As[kk+3][m] = va.w;
        } else {
            int kk = tid >> 5;
            int m  = (tid & 31) * 4;
            float4 va = *(const float4*)(A + (long)(k0 + kk) * lda + m0 + m);
            *(float4*)&As[kk][m] = va;
        }
        // ---- load B tile -> Bs[k][n] ----
        if (BM == 0) {
            int kk = tid >> 5;
            int n  = (tid & 31) * 4;
            float4 vb = *(const float4*)(B + (long)(k0 + kk) * ldb + n0 + n);
            *(float4*)&Bs[kk][n] = vb;
        } else {
            int n  = tid >> 1;
            int kk = (tid & 1) * 4;
            float4 vb = *(const float4*)(B + (long)(n0 + n) * ldb + k0 + kk);
            Bs[kk+0][n] = vb.x; Bs[kk+1][n] = vb.y;
            Bs[kk+2][n] = vb.z; Bs[kk+3][n] = vb.w;
        }
        __syncthreads();

        #pragma unroll
        for (int kk = 0; kk < KTILE; kk++) {
            float a[8], b[8];
            *(float4*)&a[0] = *(const float4*)&As[kk][ty*8];
            *(float4*)&a[4] = *(const float4*)&As[kk][ty*8+4];
            *(float4*)&b[0] = *(const float4*)&Bs[kk][tx*8];
            *(float4*)&b[4] = *(const float4*)&Bs[kk][tx*8+4];
            #pragma unroll
            for (int i = 0; i < 8; i++)
                #pragma unroll
                for (int j = 0; j < 8; j++)
                    acc[i][j] += a[i] * b[j];
        }
        __syncthreads();
    }

    float bv[8];
    #pragma unroll
    for (int j = 0; j < 8; j++)
        bv[j] = bias ? bias[n0 + tx*8 + j] : 0.f;

    #pragma unroll
    for (int i = 0; i < 8; i++) {
        long row = (long)(m0 + ty*8 + i) * ldc;
        float4 o0, o1;
        o0.x = acc[i][0]*alpha + bv[0]; o0.y = acc[i][1]*alpha + bv[1];
        o0.z = acc[i][2]*alpha + bv[2]; o0.w = acc[i][3]*alpha + bv[3];
        o1.x = acc[i][4]*alpha + bv[4]; o1.y = acc[i][5]*alpha + bv[5];
        o1.z = acc[i][6]*alpha + bv[6]; o1.w = acc[i][7]*alpha + bv[7];
        *(float4*)(C + row + n0 + tx*8)     = o0;
        *(float4*)(C + row + n0 + tx*8 + 4) = o1;
    }
}

// ---------------------------------------------------------------------------
// Elementwise / reduction kernels
// ---------------------------------------------------------------------------
__device__ __forceinline__ float warp_sum(float v) {
    #pragma unroll
    for (int o = 16; o > 0; o >>= 1) v += __shfl_xor_sync(0xffffffffu, v, o);
    return v;
}
__device__ __forceinline__ float warp_max(float v) {
    #pragma unroll
    for (int o = 16; o > 0; o >>= 1) v = fmaxf(v, __shfl_xor_sync(0xffffffffu, v, o));
    return v;
}
__device__ __forceinline__ float gelu1(float x) {
    return 0.5f * x * (1.f + erff(x * 0.70710678118654752f));
}

// LayerNorm over C=1024. One block (256 thr, 4 elems each) per row.
__global__ void ln_kernel(const float* __restrict__ in, float* __restrict__ out,
                          const float* __restrict__ g, const float* __restrict__ b)
{
    long row = blockIdx.x;
    const float4* r4 = (const float4*)(in + row * CC);
    float4 v = r4[threadIdx.x];
    float s  = v.x + v.y + v.z + v.w;
    float ss = v.x*v.x + v.y*v.y + v.z*v.z + v.w*v.w;
    __shared__ float sm[16];
    s = warp_sum(s); ss = warp_sum(ss);
    int w = threadIdx.x >> 5, l = threadIdx.x & 31;
    if (l == 0) { sm[w] = s; sm[8+w] = ss; }
    __syncthreads();
    float tot = 0.f, tots = 0.f;
    #pragma unroll
    for (int i = 0; i < 8; i++) { tot += sm[i]; tots += sm[8+i]; }
    float mu  = tot * (1.f/CC);
    float var = tots * (1.f/CC) - mu*mu;
    float r   = rsqrtf(var + 1e-5f);
    float4 gv = ((const float4*)g)[threadIdx.x];
    float4 bv = ((const float4*)b)[threadIdx.x];
    float4 o;
    o.x = (v.x - mu)*r*gv.x + bv.x;
    o.y = (v.y - mu)*r*gv.y + bv.y;
    o.z = (v.z - mu)*r*gv.z + bv.z;
    o.w = (v.w - mu)*r*gv.w + bv.w;
    ((float4*)(out + row * CC))[threadIdx.x] = o;
}

// Softmax over last dim C=1024 (in place). One block per row.
__global__ void softmax_kernel(float* __restrict__ x)
{
    long row = blockIdx.x;
    float4* r4 = (float4*)(x + row * CC);
    float4 v = r4[threadIdx.x];
    float m = fmaxf(fmaxf(v.x, v.y), fmaxf(v.z, v.w));
    __shared__ float sm[8];
    m = warp_max(m);
    int w = threadIdx.x >> 5, l = threadIdx.x & 31;
    if (l == 0) sm[w] = m;
    __syncthreads();
    float M = sm[0];
    #pragma unroll
    for (int i = 1; i < 8; i++) M = fmaxf(M, sm[i]);
    __syncthreads();
    float4 e;
    e.x = expf(v.x - M); e.y = expf(v.y - M);
    e.z = expf(v.z - M); e.w = expf(v.w - M);
    float s = warp_sum(e.x + e.y + e.z + e.w);
    if (l == 0) sm[w] = s;
    __syncthreads();
    float tot = 0.f;
    #pragma unroll
    for (int i = 0; i < 8; i++) tot += sm[i];
    float inv = 1.f / tot;
    e.x *= inv; e.y *= inv; e.z *= inv; e.w *= inv;
    r4[threadIdx.x] = e;
}

// In-place exact GELU over n4 float4s.
__global__ void gelu_kernel(float* __restrict__ x, long n4)
{
    long i = (long)blockIdx.x * blockDim.x + threadIdx.x;
    if (i >= n4) return;
    float4 v = ((float4*)x)[i];
    v.x = gelu1(v.x); v.y = gelu1(v.y); v.z = gelu1(v.z); v.w = gelu1(v.w);
    ((float4*)x)[i] = v;
}

// h = gelu(t) (+ pred if !first); pred captured on first layer.
__global__ void gelu_combine_kernel(const float* __restrict__ t,
                                    float* __restrict__ pred,
                                    float* __restrict__ h, int first, long n4)
{
    long i = (long)blockIdx.x * blockDim.x + threadIdx.x;
    if (i >= n4) return;
    float4 v = ((const float4*)t)[i];
    v.x = gelu1(v.x); v.y = gelu1(v.y); v.z = gelu1(v.z); v.w = gelu1(v.w);
    if (first) {
        ((float4*)pred)[i] = v;
        ((float4*)h)[i] = v;
    } else {
        float4 p = ((const float4*)pred)[i];
        v.x += p.x; v.y += p.y; v.z += p.z; v.w += p.w;
        ((float4*)h)[i] = v;
    }
}

// out[b,s,c] += (s even ? sin : cos)(s * 1000^{-2c/C})
__global__ void pe_add_kernel(float* __restrict__ out)
{
    long idx = (long)blockIdx.x * blockDim.x + threadIdx.x;
    if (idx >= (long)MROWS * CC) return;
    int c = (int)(idx & (CC-1));
    int s = (int)((idx >> 10) & (SS-1));
    // 2*log2(1000)/1024 = 0.0194644224310...
    float inv = exp2f(-0.0194644224310f * (float)c);
    float arg = (float)s * inv;
    out[idx] += (s & 1) ? cosf(arg) : sinf(arg);
}

// ---------------------------------------------------------------------------
// Host orchestration (graph-capturable: kernel launches only)
// ---------------------------------------------------------------------------
extern "C" void kernel_launch(void* const* d_in, const int* in_sizes, int n_in,
                              void* d_out, int out_size)
{
    const float* x        = (const float*)d_in[0];
    const float* fc_in_w  = (const float*)d_in[1];
    const float* fc_in_b  = (const float*)d_in[2];
    const float* ln_g     = (const float*)d_in[3];
    const float* ln_b     = (const float*)d_in[4];
    const float* qkv_w    = (const float*)d_in[5];
    const float* qkv_b    = (const float*)d_in[6];
    const float* proj_w   = (const float*)d_in[7];
    const float* proj_b   = (const float*)d_in[8];
    const float* fc_out_w = (const float*)d_in[9];
    const float* fc_out_b = (const float*)d_in[10];
    float* out = (float*)d_out;

    float *h, *tmp, *pred, *att, *qkv, *kv;
    cudaGetSymbolAddress((void**)&h,    g_h);
    cudaGetSymbolAddress((void**)&tmp,  g_tmp);
    cudaGetSymbolAddress((void**)&pred, g_pred);
    cudaGetSymbolAddress((void**)&att,  g_att);
    cudaGetSymbolAddress((void**)&qkv,  g_qkv);
    cudaGetSymbolAddress((void**)&kv,   g_kv);

    const long n4_h   = (long)MROWS * CC / 4;     // 2,097,152
    const long n4_qkv = (long)MROWS * C3 / 4;     // 6,291,456

    // 1) tmp = x @ fc_in_w^T + fc_in_b
    sgemm<0,1><<<dim3(CC/TILE, MROWS/TILE, 1), 256>>>(
        x, fc_in_w, fc_in_b, tmp,
        MROWS, CC, CC, CC, CC, CC, 0, 0, 0, 1.f);

    // 2) h = LN(tmp)
    ln_kernel<<<MROWS, 256>>>(tmp, h, ln_g, ln_b);

    for (int i = 0; i < HH; i++) {
        const float* Wq = qkv_w + (long)i * C3 * CC;
        const float* bq = qkv_b + (long)i * C3;
        const float* Wp = proj_w + (long)i * CC * CC;
        const float* bp = proj_b + (long)i * CC;

        // 3) qkv = h @ Wq^T + bq     [8192 x 3072]
        sgemm<0,1><<<dim3(C3/TILE, MROWS/TILE, 1), 256>>>(
            h, Wq, bq, qkv,
            MROWS, C3, CC, CC, CC, C3, 0, 0, 0, 1.f);

        // 4) qkv = gelu(qkv)
        gelu_kernel<<<(unsigned)((n4_qkv + 255) / 256), 256>>>(qkv, n4_qkv);

        // 5) kv[b] = k[b]^T @ v[b]   (batched over B; [C x C], K = S)
        //    k rows at qkv + b*S*3C + C (lda=3C), v at +2C
        sgemm<1,0><<<dim3(CC/TILE, CC/TILE, BB), 256>>>(
            qkv + CC, qkv + 2*CC, (const float*)nullptr, kv,
            CC, CC, SS, C3, C3, CC,
            (long)SS * C3, (long)SS * C3, (long)CC * CC, 1.f);

        // 6) att[b] = (q[b] @ kv[b]) / C   (batched; [S x C], K = C)
        sgemm<0,0><<<dim3(CC/TILE, SS/TILE, BB), 256>>>(
            qkv, kv, (const float*)nullptr, att,
            SS, CC, CC, C3, CC, CC,
            (long)SS * C3, (long)CC * CC, (long)SS * CC, 1.f / (float)CC);

        // 7) softmax over C (in place)
        softmax_kernel<<<MROWS, 256>>>(att);

        // 8) tmp = att @ Wp^T + bp
        sgemm<0,1><<<dim3(CC/TILE, MROWS/TILE, 1), 256>>>(
            att, Wp, bp, tmp,
            MROWS, CC, CC, CC, CC, CC, 0, 0, 0, 1.f);

        // 9) h = gelu(tmp) (+ pred for i>0); pred = gelu(tmp) at i==0
        gelu_combine_kernel<<<(unsigned)((n4_h + 255) / 256), 256>>>(
            tmp, pred, h, (i == 0) ? 1 : 0, n4_h);
    }

    // 10) out = h @ fc_out_w^T + fc_out_b
    sgemm<0,1><<<dim3(CC/TILE, MROWS/TILE, 1), 256>>>(
        h, fc_out_w, fc_out_b, out,
        MROWS, CC, CC, CC, CC, CC, 0, 0, 0, 1.f);

    // 11) out += positional encoding
    pe_add_kernel<<<(unsigned)(((long)MROWS * CC + 255) / 256), 256>>>(out);
}

// round 5
// speedup vs baseline: 1.9063x; 1.9063x over previous
#include <cuda_runtime.h>
#include <cuda_bf16.h>
#include <math.h>
#include <stdint.h>

// Problem constants
#define BB 4
#define SS 2048
#define CC 1024
#define HH 4
#define MROWS (BB*SS)        // 8192
#define C3 (3*CC)            // 3072

// ---------------------------------------------------------------------------
// Scratch (static device globals; no runtime allocation)
// ---------------------------------------------------------------------------
__device__ float g_h   [MROWS*(long)CC];
__device__ float g_tmp [MROWS*(long)CC];
__device__ float g_pred[MROWS*(long)CC];
__device__ float g_att [MROWS*(long)CC];
__device__ float g_qkv [MROWS*(long)C3];
__device__ float g_kv  [BB*(long)CC*CC];   // kvT = v^T k  per batch

// ---------------------------------------------------------------------------
// Helpers
// ---------------------------------------------------------------------------
__device__ __forceinline__ uint32_t smem_u32(const void* p) {
    uint32_t a;
    asm("{ .reg .u64 t; cvta.to.shared.u64 t, %1; cvt.u32.u64 %0, t; }" : "=r"(a) : "l"(p));
    return a;
}
__device__ __forceinline__ uint16_t b16(float f) {
    __nv_bfloat16 h = __float2bfloat16_rn(f);
    return reinterpret_cast<uint16_t&>(h);
}
__device__ __forceinline__ float fb16(uint16_t u) {
    __nv_bfloat16 h = reinterpret_cast<__nv_bfloat16&>(u);
    return __bfloat162float(h);
}
__device__ __forceinline__ void ldsm4(uint32_t* r, uint32_t addr) {
    asm volatile("ldmatrix.sync.aligned.m8n8.x4.shared.b16 {%0,%1,%2,%3}, [%4];"
                 : "=r"(r[0]), "=r"(r[1]), "=r"(r[2]), "=r"(r[3]) : "r"(addr));
}
__device__ __forceinline__ void mma16816(float* c, const uint32_t* a, const uint32_t* b) {
    asm volatile(
        "mma.sync.aligned.m16n8k16.row.col.f32.bf16.bf16.f32 "
        "{%0,%1,%2,%3}, {%4,%5,%6,%7}, {%8,%9}, {%0,%1,%2,%3};"
        : "+f"(c[0]), "+f"(c[1]), "+f"(c[2]), "+f"(c[3])
        : "r"(a[0]), "r"(a[1]), "r"(a[2]), "r"(a[3]), "r"(b[0]), "r"(b[1]));
}
__device__ __forceinline__ float gelu1(float x) {
    return 0.5f * x * (1.f + erff(x * 0.70710678118654752f));
}

// hi/lo split of 4 floats, packed as 2x uint32 (2 bf16 each)
__device__ __forceinline__ void cvt_hl(float4 v, uint2& h, uint2& l) {
    uint16_t hx = b16(v.x), hy = b16(v.y), hz = b16(v.z), hw = b16(v.w);
    uint16_t lx = b16(v.x - fb16(hx)), ly = b16(v.y - fb16(hy));
    uint16_t lz = b16(v.z - fb16(hz)), lw = b16(v.w - fb16(hw));
    h.x = (uint32_t)hx | ((uint32_t)hy << 16);
    h.y = (uint32_t)hz | ((uint32_t)hw << 16);
    l.x = (uint32_t)lx | ((uint32_t)ly << 16);
    l.y = (uint32_t)lz | ((uint32_t)lw << 16);
}

// ---------------------------------------------------------------------------
// bf16x3-emulated fp32 GEMM on legacy tensor pipe (mma.sync m16n8k16)
//   C[m,n] = alpha * sum_k op(A)[m,k]*op(B)[k,n] + bias[n]  (+ optional GELU)
//   AM==0: A[m,k]=A[m*lda+k] (k-contig)   AM==1: A[m,k]=A[k*lda+m] (m-contig)
//   BM==1: B[k,n]=B[n*ldb+k] (k-contig)   BM==0: B[k,n]=B[k*ldb+n] (n-contig)
// CTA 128x128, KT=32, 256 threads (8 warps, warp tile 64m x 32n).
// smem: A/B tiles stored k-contiguous as [128][40] bf16 (hi & lo planes).
// ---------------------------------------------------------------------------
#define KT 32
#define SLD 40   // smem row stride in bf16 (80B: conflict-free ldmatrix)

template<int AM, int BM, int ACT>
__global__ void __launch_bounds__(256)
hgemm(const float* __restrict__ Ag, const float* __restrict__ Bg,
      const float* __restrict__ bias, float* __restrict__ Cg,
      int K, int lda, int ldb, int ldc,
      long sA, long sB, long sC, float alpha)
{
    __shared__ __align__(16) uint16_t sAh[128*SLD];
    __shared__ __align__(16) uint16_t sAl[128*SLD];
    __shared__ __align__(16) uint16_t sBh[128*SLD];
    __shared__ __align__(16) uint16_t sBl[128*SLD];

    const int tid  = threadIdx.x;
    const int lane = tid & 31;
    const int wid  = tid >> 5;
    const int m0 = blockIdx.y * 128;
    const int n0 = blockIdx.x * 128;
    const int wm = (wid & 1) * 64;     // warp m offset
    const int wn = (wid >> 1) * 32;    // warp n offset

    const float* A = Ag + (long)blockIdx.z * sA;
    const float* B = Bg + (long)blockIdx.z * sB;
    float*       C = Cg + (long)blockIdx.z * sC;

    float acc[4][4][4];
    #pragma unroll
    for (int i = 0; i < 4; i++)
        #pragma unroll
        for (int j = 0; j < 4; j++)
            #pragma unroll
            for (int e = 0; e < 4; e++) acc[i][j][e] = 0.f;

    // producer coordinates
    const int rowC = tid >> 1;              // contig case: smem row
    const int kbC  = (tid & 1) * 16;        // contig case: k base
    const int kkS  = tid >> 3;              // scatter case: k (0..31)
    const int mbS  = (tid & 7) * 4;         // scatter case: m base

    float4 ra[4], rb[4];

    auto loadA = [&](int k0) {
        #pragma unroll
        for (int j = 0; j < 4; j++) {
            if (AM == 0) ra[j] = *(const float4*)(A + (long)(m0 + rowC) * lda + k0 + kbC + j*4);
            else         ra[j] = *(const float4*)(A + (long)(k0 + kkS) * lda + m0 + mbS + j*32);
        }
    };
    auto loadB = [&](int k0) {
        #pragma unroll
        for (int j = 0; j < 4; j++) {
            if (BM == 1) rb[j] = *(const float4*)(B + (long)(n0 + rowC) * ldb + k0 + kbC + j*4);
            else         rb[j] = *(const float4*)(B + (long)(k0 + kkS) * ldb + n0 + mbS + j*32);
        }
    };
    auto storeA = [&]() {
        if (AM == 0) {
            #pragma unroll
            for (int j = 0; j < 4; j++) {
                uint2 h, l; cvt_hl(ra[j], h, l);
                int off = rowC*SLD + kbC + j*4;
                *(uint2*)&sAh[off] = h;
                *(uint2*)&sAl[off] = l;
            }
        } else {
            #pragma unroll
            for (int j = 0; j < 4; j++) {
                const float v[4] = {ra[j].x, ra[j].y, ra[j].z, ra[j].w};
                #pragma unroll
                for (int e = 0; e < 4; e++) {
                    int m = mbS + j*32 + e;
                    uint16_t hv = b16(v[e]);
                    sAh[m*SLD + kkS] = hv;
                    sAl[m*SLD + kkS] = b16(v[e] - fb16(hv));
                }
            }
        }
    };
    auto storeB = [&]() {
        if (BM == 1) {
            #pragma unroll
            for (int j = 0; j < 4; j++) {
                uint2 h, l; cvt_hl(rb[j], h, l);
                int off = rowC*SLD + kbC + j*4;
                *(uint2*)&sBh[off] = h;
                *(uint2*)&sBl[off] = l;
            }
        } else {
            #pragma unroll
            for (int j = 0; j < 4; j++) {
                const float v[4] = {rb[j].x, rb[j].y, rb[j].z, rb[j].w};
                #pragma unroll
                for (int e = 0; e < 4; e++) {
                    int n = mbS + j*32 + e;
                    uint16_t hv = b16(v[e]);
                    sBh[n*SLD + kkS] = hv;
                    sBl[n*SLD + kkS] = b16(v[e] - fb16(hv));
                }
            }
        }
    };

    const uint32_t bAh = smem_u32(sAh), bAl = smem_u32(sAl);
    const uint32_t bBh = smem_u32(sBh), bBl = smem_u32(sBl);

    // ldmatrix lane addressing
    const int arow = lane & 15;
    const int akof = (lane >> 4) * 8;
    const int brow = ((lane >> 4) * 8) + (lane & 7);
    const int bkof = ((lane >> 3) & 1) * 8;

    const int nt = K / KT;
    loadA(0); loadB(0);

    for (int t = 0; t < nt; t++) {
        __syncthreads();                 // consumers of previous tile done
        storeA(); storeB();
        __syncthreads();
        if (t + 1 < nt) { loadA((t+1)*KT); loadB((t+1)*KT); }  // overlap mma

        #pragma unroll
        for (int ks = 0; ks < 2; ks++) {
            uint32_t ah[4][4], al[4][4], bh[4][2], bl[4][2];
            #pragma unroll
            for (int mt = 0; mt < 4; mt++) {
                uint32_t off = (uint32_t)(((wm + mt*16 + arow)*SLD + ks*16 + akof) * 2);
                ldsm4(ah[mt], bAh + off);
                ldsm4(al[mt], bAl + off);
            }
            #pragma unroll
            for (int np = 0; np < 2; np++) {
                uint32_t off = (uint32_t)(((wn + np*16 + brow)*SLD + ks*16 + bkof) * 2);
                uint32_t r[4];
                ldsm4(r, bBh + off);
                bh[2*np][0] = r[0]; bh[2*np][1] = r[1];
                bh[2*np+1][0] = r[2]; bh[2*np+1][1] = r[3];
                ldsm4(r, bBl + off);
                bl[2*np][0] = r[0]; bl[2*np][1] = r[1];
                bl[2*np+1][0] = r[2]; bl[2*np+1][1] = r[3];
            }
            #pragma unroll
            for (int mt = 0; mt < 4; mt++)
                #pragma unroll
                for (int ntl = 0; ntl < 4; ntl++) {
                    mma16816(acc[mt][ntl], ah[mt], bh[ntl]);
                    mma16816(acc[mt][ntl], ah[mt], bl[ntl]);
                    mma16816(acc[mt][ntl], al[mt], bh[ntl]);
                }
        }
    }

    // -------- epilogue (register fragments -> gmem) --------
    const int r  = lane >> 2;
    const int cp = (lane & 3) * 2;
    #pragma unroll
    for (int mt = 0; mt < 4; mt++) {
        #pragma unroll
        for (int ntl = 0; ntl < 4; ntl++) {
            int col = n0 + wn + ntl*8 + cp;
            float b0 = 0.f, b1 = 0.f;
            if (bias) { float2 bb = *(const float2*)(bias + col); b0 = bb.x; b1 = bb.y; }
            float v0 = acc[mt][ntl][0]*alpha + b0;
            float v1 = acc[mt][ntl][1]*alpha + b1;
            float v2 = acc[mt][ntl][2]*alpha + b0;
            float v3 = acc[mt][ntl][3]*alpha + b1;
            if (ACT == 1) { v0 = gelu1(v0); v1 = gelu1(v1); v2 = gelu1(v2); v3 = gelu1(v3); }
            long g0 = (long)(m0 + wm + mt*16 + r) * ldc + col;
            long g1 = g0 + 8L*ldc;
            *(float2*)(C + g0) = make_float2(v0, v1);
            *(float2*)(C + g1) = make_float2(v2, v3);
        }
    }
}

// ---------------------------------------------------------------------------
// Elementwise kernels
// ---------------------------------------------------------------------------
__device__ __forceinline__ float warp_sum(float v) {
    #pragma unroll
    for (int o = 16; o > 0; o >>= 1) v += __shfl_xor_sync(0xffffffffu, v, o);
    return v;
}
__device__ __forceinline__ float warp_max(float v) {
    #pragma unroll
    for (int o = 16; o > 0; o >>= 1) v = fmaxf(v, __shfl_xor_sync(0xffffffffu, v, o));
    return v;
}

__global__ void ln_kernel(const float* __restrict__ in, float* __restrict__ out,
                          const float* __restrict__ g, const float* __restrict__ b)
{
    long row = blockIdx.x;
    const float4* r4 = (const float4*)(in + row * CC);
    float4 v = r4[threadIdx.x];
    float s  = v.x + v.y + v.z + v.w;
    float ss = v.x*v.x + v.y*v.y + v.z*v.z + v.w*v.w;
    __shared__ float sm[16];
    s = warp_sum(s); ss = warp_sum(ss);
    int w = threadIdx.x >> 5, l = threadIdx.x & 31;
    if (l == 0) { sm[w] = s; sm[8+w] = ss; }
    __syncthreads();
    float tot = 0.f, tots = 0.f;
    #pragma unroll
    for (int i = 0; i < 8; i++) { tot += sm[i]; tots += sm[8+i]; }
    float mu  = tot * (1.f/CC);
    float var = tots * (1.f/CC) - mu*mu;
    float rr  = rsqrtf(var + 1e-5f);
    float4 gv = ((const float4*)g)[threadIdx.x];
    float4 bv = ((const float4*)b)[threadIdx.x];
    float4 o;
    o.x = (v.x - mu)*rr*gv.x + bv.x;
    o.y = (v.y - mu)*rr*gv.y + bv.y;
    o.z = (v.z - mu)*rr*gv.z + bv.z;
    o.w = (v.w - mu)*rr*gv.w + bv.w;
    ((float4*)(out + row * CC))[threadIdx.x] = o;
}

__global__ void softmax_kernel(float* __restrict__ x)
{
    long row = blockIdx.x;
    float4* r4 = (float4*)(x + row * CC);
    float4 v = r4[threadIdx.x];
    float m = fmaxf(fmaxf(v.x, v.y), fmaxf(v.z, v.w));
    __shared__ float sm[8];
    m = warp_max(m);
    int w = threadIdx.x >> 5, l = threadIdx.x & 31;
    if (l == 0) sm[w] = m;
    __syncthreads();
    float M = sm[0];
    #pragma unroll
    for (int i = 1; i < 8; i++) M = fmaxf(M, sm[i]);
    __syncthreads();
    float4 e;
    e.x = expf(v.x - M); e.y = expf(v.y - M);
    e.z = expf(v.z - M); e.w = expf(v.w - M);
    float s = warp_sum(e.x + e.y + e.z + e.w);
    if (l == 0) sm[w] = s;
    __syncthreads();
    float tot = 0.f;
    #pragma unroll
    for (int i = 0; i < 8; i++) tot += sm[i];
    float inv = 1.f / tot;
    e.x *= inv; e.y *= inv; e.z *= inv; e.w *= inv;
    r4[threadIdx.x] = e;
}

// h = t (+ pred if !first); pred captured on first layer. (gelu fused in GEMM)
__global__ void combine_kernel(const float* __restrict__ t,
                               float* __restrict__ pred,
                               float* __restrict__ h, int first, long n4)
{
    long i = (long)blockIdx.x * blockDim.x + threadIdx.x;
    if (i >= n4) return;
    float4 v = ((const float4*)t)[i];
    if (first) {
        ((float4*)pred)[i] = v;
        ((float4*)h)[i] = v;
    } else {
        float4 p = ((const float4*)pred)[i];
        v.x += p.x; v.y += p.y; v.z += p.z; v.w += p.w;
        ((float4*)h)[i] = v;
    }
}

__global__ void pe_add_kernel(float* __restrict__ out)
{
    long idx = (long)blockIdx.x * blockDim.x + threadIdx.x;
    if (idx >= (long)MROWS * CC) return;
    int c = (int)(idx & (CC-1));
    int s = (int)((idx >> 10) & (SS-1));
    float inv = exp2f(-0.0194644224310f * (float)c);
    float arg = (float)s * inv;
    out[idx] += (s & 1) ? cosf(arg) : sinf(arg);
}

// ---------------------------------------------------------------------------
// Host orchestration (graph-capturable)
// ---------------------------------------------------------------------------
extern "C" void kernel_launch(void* const* d_in, const int* in_sizes, int n_in,
                              void* d_out, int out_size)
{
    const float* x        = (const float*)d_in[0];
    const float* fc_in_w  = (const float*)d_in[1];
    const float* fc_in_b  = (const float*)d_in[2];
    const float* ln_g     = (const float*)d_in[3];
    const float* ln_b     = (const float*)d_in[4];
    const float* qkv_w    = (const float*)d_in[5];
    const float* qkv_b    = (const float*)d_in[6];
    const float* proj_w   = (const float*)d_in[7];
    const float* proj_b   = (const float*)d_in[8];
    const float* fc_out_w = (const float*)d_in[9];
    const float* fc_out_b = (const float*)d_in[10];
    float* out = (float*)d_out;

    float *h, *tmp, *pred, *att, *qkv, *kv;
    cudaGetSymbolAddress((void**)&h,    g_h);
    cudaGetSymbolAddress((void**)&tmp,  g_tmp);
    cudaGetSymbolAddress((void**)&pred, g_pred);
    cudaGetSymbolAddress((void**)&att,  g_att);
    cudaGetSymbolAddress((void**)&qkv,  g_qkv);
    cudaGetSymbolAddress((void**)&kv,   g_kv);

    const long n4_h = (long)MROWS * CC / 4;

    // 1) tmp = x @ fc_in_w^T + fc_in_b
    hgemm<0,1,0><<<dim3(CC/128, MROWS/128, 1), 256>>>(
        x, fc_in_w, fc_in_b, tmp, CC, CC, CC, CC, 0, 0, 0, 1.f);

    // 2) h = LN(tmp)
    ln_kernel<<<MROWS, 256>>>(tmp, h, ln_g, ln_b);

    for (int i = 0; i < HH; i++) {
        const float* Wq = qkv_w + (long)i * C3 * CC;
        const float* bq = qkv_b + (long)i * C3;
        const float* Wp = proj_w + (long)i * CC * CC;
        const float* bp = proj_b + (long)i * CC;

        // 3) qkv = gelu(h @ Wq^T + bq)   [8192 x 3072]
        hgemm<0,1,1><<<dim3(C3/128, MROWS/128, 1), 256>>>(
            h, Wq, bq, qkv, CC, CC, CC, C3, 0, 0, 0, 1.f);

        // 4) kvT[b] = v[b]^T @ k[b]    [C x C], K = S   (A m-contig, B n-contig)
        //    kvT[cv][ck] = sum_s v[s][cv] * k[s][ck]
        hgemm<1,0,0><<<dim3(CC/128, CC/128, BB), 256>>>(
            qkv + 2*CC, qkv + CC, (const float*)nullptr, kv,
            SS, C3, C3, CC,
            (long)SS * C3, (long)SS * C3, (long)CC * CC, 1.f);

        // 5) att[b] = (q[b] @ kvT[b]^T) / C   [S x C], K = C  (B k-contig -> mode1)
        hgemm<0,1,0><<<dim3(CC/128, SS/128, BB), 256>>>(
            qkv, kv, (const float*)nullptr, att,
            CC, C3, CC, CC,
            (long)SS * C3, (long)CC * CC, (long)SS * CC, 1.f / (float)CC);

        // 6) softmax over C (in place)
        softmax_kernel<<<MROWS, 256>>>(att);

        // 7) tmp = gelu(att @ Wp^T + bp)
        hgemm<0,1,1><<<dim3(CC/128, MROWS/128, 1), 256>>>(
            att, Wp, bp, tmp, CC, CC, CC, CC, 0, 0, 0, 1.f);

        // 8) h = tmp (+ pred for i>0); pred = tmp at i==0
        combine_kernel<<<(unsigned)((n4_h + 255) / 256), 256>>>(
            tmp, pred, h, (i == 0) ? 1 : 0, n4_h);
    }

    // 9) out = h @ fc_out_w^T + fc_out_b
    hgemm<0,1,0><<<dim3(CC/128, MROWS/128, 1), 256>>>(
        h, fc_out_w, fc_out_b, out, CC, CC, CC, CC, 0, 0, 0, 1.f);

    // 10) out += positional encoding
    pe_add_kernel<<<(unsigned)(((long)MROWS * CC + 255) / 256), 256>>>(out);
}

// round 6
// speedup vs baseline: 2.1305x; 1.1176x over previous
#include <cuda_runtime.h>
#include <cuda_bf16.h>
#include <math.h>
#include <stdint.h>

// Problem constants
#define BB 4
#define SS 2048
#define CC 1024
#define HH 4
#define MROWS (BB*SS)        // 8192
#define C3 (3*CC)            // 3072

// ---------------------------------------------------------------------------
// Scratch (static device globals; no runtime allocation)
// ---------------------------------------------------------------------------
__device__ float g_h   [MROWS*(long)CC];
__device__ float g_tmp [MROWS*(long)CC];
__device__ float g_pred[MROWS*(long)CC];
__device__ float g_att [MROWS*(long)CC];
__device__ float g_qkv [MROWS*(long)C3];
__device__ float g_kv  [BB*(long)CC*CC];   // kvT = v^T k  per batch

// ---------------------------------------------------------------------------
// Helpers
// ---------------------------------------------------------------------------
__device__ __forceinline__ uint32_t smem_u32(const void* p) {
    uint32_t a;
    asm("{ .reg .u64 t; cvta.to.shared.u64 t, %1; cvt.u32.u64 %0, t; }" : "=r"(a) : "l"(p));
    return a;
}
__device__ __forceinline__ uint16_t b16(float f) {
    __nv_bfloat16 h = __float2bfloat16_rn(f);
    return reinterpret_cast<uint16_t&>(h);
}
__device__ __forceinline__ float fb16(uint16_t u) {
    __nv_bfloat16 h = reinterpret_cast<__nv_bfloat16&>(u);
    return __bfloat162float(h);
}
__device__ __forceinline__ void ldsm4(uint32_t* r, uint32_t addr) {
    asm volatile("ldmatrix.sync.aligned.m8n8.x4.shared.b16 {%0,%1,%2,%3}, [%4];"
                 : "=r"(r[0]), "=r"(r[1]), "=r"(r[2]), "=r"(r[3]) : "r"(addr));
}
__device__ __forceinline__ void mma16816(float* c, const uint32_t* a, const uint32_t* b) {
    asm volatile(
        "mma.sync.aligned.m16n8k16.row.col.f32.bf16.bf16.f32 "
        "{%0,%1,%2,%3}, {%4,%5,%6,%7}, {%8,%9}, {%0,%1,%2,%3};"
        : "+f"(c[0]), "+f"(c[1]), "+f"(c[2]), "+f"(c[3])
        : "r"(a[0]), "r"(a[1]), "r"(a[2]), "r"(a[3]), "r"(b[0]), "r"(b[1]));
}
__device__ __forceinline__ float gelu1(float x) {
    return 0.5f * x * (1.f + erff(x * 0.70710678118654752f));
}

// hi/lo split of 4 floats, packed as 2x uint32 (2 bf16 each)
__device__ __forceinline__ void cvt_hl(float4 v, uint2& h, uint2& l) {
    uint16_t hx = b16(v.x), hy = b16(v.y), hz = b16(v.z), hw = b16(v.w);
    uint16_t lx = b16(v.x - fb16(hx)), ly = b16(v.y - fb16(hy));
    uint16_t lz = b16(v.z - fb16(hz)), lw = b16(v.w - fb16(hw));
    h.x = (uint32_t)hx | ((uint32_t)hy << 16);
    h.y = (uint32_t)hz | ((uint32_t)hw << 16);
    l.x = (uint32_t)lx | ((uint32_t)ly << 16);
    l.y = (uint32_t)lz | ((uint32_t)lw << 16);
}

// ---------------------------------------------------------------------------
// bf16x3-emulated fp32 GEMM on tensor pipe (mma.sync m16n8k16)
//   C[m,n] = alpha * sum_k op(A)[m,k]*op(B)[k,n] + bias[n]  (+ optional GELU)
//   AM==0: A[m,k]=A[m*lda+k] (k-contig)   AM==1: A[m,k]=A[k*lda+m] (m-contig)
//   BM==1: B[k,n]=B[n*ldb+k] (k-contig)   BM==0: B[k,n]=B[k*ldb+n] (n-contig)
// CTA 128x128, KT=32, 256 threads (8 warps, warp tile 64m x 32n).
// Double-buffered smem planes; ONE __syncthreads per K-tile.
// __launch_bounds__(256,2): 2 CTAs/SM for cross-CTA latency hiding.
// ---------------------------------------------------------------------------
#define KT 32
#define SLD 40                       // smem row stride in bf16
#define PL  (128*SLD)                // plane elements (uint16)
#define SMEM_BYTES (2*4*PL*2)        // 2 bufs * 4 planes * PL u16 = 81920 B

template<int AM, int BM, int ACT>
__global__ void __launch_bounds__(256, 2)
hgemm(const float* __restrict__ Ag, const float* __restrict__ Bg,
      const float* __restrict__ bias, float* __restrict__ Cg,
      int K, int lda, int ldb, int ldc,
      long sA, long sB, long sC, float alpha)
{
    extern __shared__ __align__(16) uint16_t smp[];
    // plane order per buffer: Ah, Al, Bh, Bl
    const int tid  = threadIdx.x;
    const int lane = tid & 31;
    const int wid  = tid >> 5;
    const int m0 = blockIdx.y * 128;
    const int n0 = blockIdx.x * 128;
    const int wm = (wid & 1) * 64;     // warp m offset
    const int wn = (wid >> 1) * 32;    // warp n offset

    const float* A = Ag + (long)blockIdx.z * sA;
    const float* B = Bg + (long)blockIdx.z * sB;
    float*       C = Cg + (long)blockIdx.z * sC;

    float acc[4][4][4];
    #pragma unroll
    for (int i = 0; i < 4; i++)
        #pragma unroll
        for (int j = 0; j < 4; j++)
            #pragma unroll
            for (int e = 0; e < 4; e++) acc[i][j][e] = 0.f;

    // producer coordinates
    const int rowC = tid >> 1;              // contig case: smem row
    const int kbC  = (tid & 1) * 16;        // contig case: k base
    const int kkS  = tid >> 3;              // scatter case: k (0..31)
    const int mbS  = (tid & 7) * 4;         // scatter case: m base

    float4 ra[4], rb[4];

    auto loadA = [&](int k0) {
        #pragma unroll
        for (int j = 0; j < 4; j++) {
            if (AM == 0) ra[j] = *(const float4*)(A + (long)(m0 + rowC) * lda + k0 + kbC + j*4);
            else         ra[j] = *(const float4*)(A + (long)(k0 + kkS) * lda + m0 + mbS + j*32);
        }
    };
    auto loadB = [&](int k0) {
        #pragma unroll
        for (int j = 0; j < 4; j++) {
            if (BM == 1) rb[j] = *(const float4*)(B + (long)(n0 + rowC) * ldb + k0 + kbC + j*4);
            else         rb[j] = *(const float4*)(B + (long)(k0 + kkS) * ldb + n0 + mbS + j*32);
        }
    };
    auto storeA = [&](uint16_t* sAh, uint16_t* sAl) {
        if (AM == 0) {
            #pragma unroll
            for (int j = 0; j < 4; j++) {
                uint2 h, l; cvt_hl(ra[j], h, l);
                int off = rowC*SLD + kbC + j*4;
                *(uint2*)&sAh[off] = h;
                *(uint2*)&sAl[off] = l;
            }
        } else {
            #pragma unroll
            for (int j = 0; j < 4; j++) {
                const float v[4] = {ra[j].x, ra[j].y, ra[j].z, ra[j].w};
                #pragma unroll
                for (int e = 0; e < 4; e++) {
                    int m = mbS + j*32 + e;
                    uint16_t hv = b16(v[e]);
                    sAh[m*SLD + kkS] = hv;
                    sAl[m*SLD + kkS] = b16(v[e] - fb16(hv));
                }
            }
        }
    };
    auto storeB = [&](uint16_t* sBh, uint16_t* sBl) {
        if (BM == 1) {
            #pragma unroll
            for (int j = 0; j < 4; j++) {
                uint2 h, l; cvt_hl(rb[j], h, l);
                int off = rowC*SLD + kbC + j*4;
                *(uint2*)&sBh[off] = h;
                *(uint2*)&sBl[off] = l;
            }
        } else {
            #pragma unroll
            for (int j = 0; j < 4; j++) {
                const float v[4] = {rb[j].x, rb[j].y, rb[j].z, rb[j].w};
                #pragma unroll
                for (int e = 0; e < 4; e++) {
                    int n = mbS + j*32 + e;
                    uint16_t hv = b16(v[e]);
                    sBh[n*SLD + kkS] = hv;
                    sBl[n*SLD + kkS] = b16(v[e] - fb16(hv));
                }
            }
        }
    };

    // ldmatrix lane addressing
    const int arow = lane & 15;
    const int akof = (lane >> 4) * 8;
    const int brow = ((lane >> 4) * 8) + (lane & 7);
    const int bkof = ((lane >> 3) & 1) * 8;

    const uint32_t sbase = smem_u32(smp);

    const int nt = K / KT;
    loadA(0); loadB(0);

    for (int t = 0; t < nt; t++) {
        const int p = t & 1;
        uint16_t* sAh = smp + p*4*PL;
        uint16_t* sAl = sAh + PL;
        uint16_t* sBh = sAl + PL;
        uint16_t* sBl = sBh + PL;
        const uint32_t bAh = sbase + (uint32_t)(p*4*PL)*2;
        const uint32_t bAl = bAh + PL*2;
        const uint32_t bBh = bAl + PL*2;
        const uint32_t bBl = bBh + PL*2;

        storeA(sAh, sAl); storeB(sBh, sBl);
        __syncthreads();                       // single barrier per tile
        if (t + 1 < nt) { loadA((t+1)*KT); loadB((t+1)*KT); }  // overlap mma

        #pragma unroll
        for (int ks = 0; ks < 2; ks++) {
            uint32_t bh[4][2], bl[4][2];
            #pragma unroll
            for (int np = 0; np < 2; np++) {
                uint32_t off = (uint32_t)(((wn + np*16 + brow)*SLD + ks*16 + bkof) * 2);
                uint32_t r[4];
                ldsm4(r, bBh + off);
                bh[2*np][0] = r[0]; bh[2*np][1] = r[1];
                bh[2*np+1][0] = r[2]; bh[2*np+1][1] = r[3];
                ldsm4(r, bBl + off);
                bl[2*np][0] = r[0]; bl[2*np][1] = r[1];
                bl[2*np+1][0] = r[2]; bl[2*np+1][1] = r[3];
            }
            #pragma unroll
            for (int mt = 0; mt < 4; mt++) {
                uint32_t ah[4], al[4];
                uint32_t off = (uint32_t)(((wm + mt*16 + arow)*SLD + ks*16 + akof) * 2);
                ldsm4(ah, bAh + off);
                ldsm4(al, bAl + off);
                #pragma unroll
                for (int ntl = 0; ntl < 4; ntl++) {
                    mma16816(acc[mt][ntl], ah, bh[ntl]);
                    mma16816(acc[mt][ntl], ah, bl[ntl]);
                    mma16816(acc[mt][ntl], al, bh[ntl]);
                }
            }
        }
    }

    // -------- epilogue (register fragments -> gmem) --------
    const int r  = lane >> 2;
    const int cp = (lane & 3) * 2;
    #pragma unroll
    for (int mt = 0; mt < 4; mt++) {
        #pragma unroll
        for (int ntl = 0; ntl < 4; ntl++) {
            int col = n0 + wn + ntl*8 + cp;
            float b0 = 0.f, b1 = 0.f;
            if (bias) { float2 bb = *(const float2*)(bias + col); b0 = bb.x; b1 = bb.y; }
            float v0 = acc[mt][ntl][0]*alpha + b0;
            float v1 = acc[mt][ntl][1]*alpha + b1;
            float v2 = acc[mt][ntl][2]*alpha + b0;
            float v3 = acc[mt][ntl][3]*alpha + b1;
            if (ACT == 1) { v0 = gelu1(v0); v1 = gelu1(v1); v2 = gelu1(v2); v3 = gelu1(v3); }
            long g0 = (long)(m0 + wm + mt*16 + r) * ldc + col;
            long g1 = g0 + 8L*ldc;
            *(float2*)(C + g0) = make_float2(v0, v1);
            *(float2*)(C + g1) = make_float2(v2, v3);
        }
    }
}

// ---------------------------------------------------------------------------
// Elementwise kernels
// ---------------------------------------------------------------------------
__device__ __forceinline__ float warp_sum(float v) {
    #pragma unroll
    for (int o = 16; o > 0; o >>= 1) v += __shfl_xor_sync(0xffffffffu, v, o);
    return v;
}
__device__ __forceinline__ float warp_max(float v) {
    #pragma unroll
    for (int o = 16; o > 0; o >>= 1) v = fmaxf(v, __shfl_xor_sync(0xffffffffu, v, o));
    return v;
}

__global__ void ln_kernel(const float* __restrict__ in, float* __restrict__ out,
                          const float* __restrict__ g, const float* __restrict__ b)
{
    long row = blockIdx.x;
    const float4* r4 = (const float4*)(in + row * CC);
    float4 v = r4[threadIdx.x];
    float s  = v.x + v.y + v.z + v.w;
    float ss = v.x*v.x + v.y*v.y + v.z*v.z + v.w*v.w;
    __shared__ float sm[16];
    s = warp_sum(s); ss = warp_sum(ss);
    int w = threadIdx.x >> 5, l = threadIdx.x & 31;
    if (l == 0) { sm[w] = s; sm[8+w] = ss; }
    __syncthreads();
    float tot = 0.f, tots = 0.f;
    #pragma unroll
    for (int i = 0; i < 8; i++) { tot += sm[i]; tots += sm[8+i]; }
    float mu  = tot * (1.f/CC);
    float var = tots * (1.f/CC) - mu*mu;
    float rr  = rsqrtf(var + 1e-5f);
    float4 gv = ((const float4*)g)[threadIdx.x];
    float4 bv = ((const float4*)b)[threadIdx.x];
    float4 o;
    o.x = (v.x - mu)*rr*gv.x + bv.x;
    o.y = (v.y - mu)*rr*gv.y + bv.y;
    o.z = (v.z - mu)*rr*gv.z + bv.z;
    o.w = (v.w - mu)*rr*gv.w + bv.w;
    ((float4*)(out + row * CC))[threadIdx.x] = o;
}

__global__ void softmax_kernel(float* __restrict__ x)
{
    long row = blockIdx.x;
    float4* r4 = (float4*)(x + row * CC);
    float4 v = r4[threadIdx.x];
    float m = fmaxf(fmaxf(v.x, v.y), fmaxf(v.z, v.w));
    __shared__ float sm[8];
    m = warp_max(m);
    int w = threadIdx.x >> 5, l = threadIdx.x & 31;
    if (l == 0) sm[w] = m;
    __syncthreads();
    float M = sm[0];
    #pragma unroll
    for (int i = 1; i < 8; i++) M = fmaxf(M, sm[i]);
    __syncthreads();
    float4 e;
    e.x = expf(v.x - M); e.y = expf(v.y - M);
    e.z = expf(v.z - M); e.w = expf(v.w - M);
    float s = warp_sum(e.x + e.y + e.z + e.w);
    if (l == 0) sm[w] = s;
    __syncthreads();
    float tot = 0.f;
    #pragma unroll
    for (int i = 0; i < 8; i++) tot += sm[i];
    float inv = 1.f / tot;
    e.x *= inv; e.y *= inv; e.z *= inv; e.w *= inv;
    r4[threadIdx.x] = e;
}

// h = t (+ pred if !first); pred captured on first layer. (gelu fused in GEMM)
__global__ void combine_kernel(const float* __restrict__ t,
                               float* __restrict__ pred,
                               float* __restrict__ h, int first, long n4)
{
    long i = (long)blockIdx.x * blockDim.x + threadIdx.x;
    if (i >= n4) return;
    float4 v = ((const float4*)t)[i];
    if (first) {
        ((float4*)pred)[i] = v;
        ((float4*)h)[i] = v;
    } else {
        float4 p = ((const float4*)pred)[i];
        v.x += p.x; v.y += p.y; v.z += p.z; v.w += p.w;
        ((float4*)h)[i] = v;
    }
}

__global__ void pe_add_kernel(float* __restrict__ out)
{
    long idx = (long)blockIdx.x * blockDim.x + threadIdx.x;
    if (idx >= (long)MROWS * CC) return;
    int c = (int)(idx & (CC-1));
    int s = (int)((idx >> 10) & (SS-1));
    float inv = exp2f(-0.0194644224310f * (float)c);
    float arg = (float)s * inv;
    out[idx] += (s & 1) ? cosf(arg) : sinf(arg);
}

// ---------------------------------------------------------------------------
// Host orchestration (graph-capturable)
// ---------------------------------------------------------------------------
extern "C" void kernel_launch(void* const* d_in, const int* in_sizes, int n_in,
                              void* d_out, int out_size)
{
    const float* x        = (const float*)d_in[0];
    const float* fc_in_w  = (const float*)d_in[1];
    const float* fc_in_b  = (const float*)d_in[2];
    const float* ln_g     = (const float*)d_in[3];
    const float* ln_b     = (const float*)d_in[4];
    const float* qkv_w    = (const float*)d_in[5];
    const float* qkv_b    = (const float*)d_in[6];
    const float* proj_w   = (const float*)d_in[7];
    const float* proj_b   = (const float*)d_in[8];
    const float* fc_out_w = (const float*)d_in[9];
    const float* fc_out_b = (const float*)d_in[10];
    float* out = (float*)d_out;

    float *h, *tmp, *pred, *att, *qkv, *kv;
    cudaGetSymbolAddress((void**)&h,    g_h);
    cudaGetSymbolAddress((void**)&tmp,  g_tmp);
    cudaGetSymbolAddress((void**)&pred, g_pred);
    cudaGetSymbolAddress((void**)&att,  g_att);
    cudaGetSymbolAddress((void**)&qkv,  g_qkv);
    cudaGetSymbolAddress((void**)&kv,   g_kv);

    cudaFuncSetAttribute(hgemm<0,1,0>, cudaFuncAttributeMaxDynamicSharedMemorySize, SMEM_BYTES);
    cudaFuncSetAttribute(hgemm<0,1,1>, cudaFuncAttributeMaxDynamicSharedMemorySize, SMEM_BYTES);
    cudaFuncSetAttribute(hgemm<1,0,0>, cudaFuncAttributeMaxDynamicSharedMemorySize, SMEM_BYTES);

    const long n4_h = (long)MROWS * CC / 4;

    // 1) tmp = x @ fc_in_w^T + fc_in_b
    hgemm<0,1,0><<<dim3(CC/128, MROWS/128, 1), 256, SMEM_BYTES>>>(
        x, fc_in_w, fc_in_b, tmp, CC, CC, CC, CC, 0, 0, 0, 1.f);

    // 2) h = LN(tmp)
    ln_kernel<<<MROWS, 256>>>(tmp, h, ln_g, ln_b);

    for (int i = 0; i < HH; i++) {
        const float* Wq = qkv_w + (long)i * C3 * CC;
        const float* bq = qkv_b + (long)i * C3;
        const float* Wp = proj_w + (long)i * CC * CC;
        const float* bp = proj_b + (long)i * CC;

        // 3) qkv = gelu(h @ Wq^T + bq)   [8192 x 3072]
        hgemm<0,1,1><<<dim3(C3/128, MROWS/128, 1), 256, SMEM_BYTES>>>(
            h, Wq, bq, qkv, CC, CC, CC, C3, 0, 0, 0, 1.f);

        // 4) kvT[b] = v[b]^T @ k[b]    [C x C], K = S   (A m-contig, B n-contig)
        hgemm<1,0,0><<<dim3(CC/128, CC/128, BB), 256, SMEM_BYTES>>>(
            qkv + 2*CC, qkv + CC, (const float*)nullptr, kv,
            SS, C3, C3, CC,
            (long)SS * C3, (long)SS * C3, (long)CC * CC, 1.f);

        // 5) att[b] = (q[b] @ kvT[b]^T) / C   [S x C], K = C  (B k-contig)
        hgemm<0,1,0><<<dim3(CC/128, SS/128, BB), 256, SMEM_BYTES>>>(
            qkv, kv, (const float*)nullptr, att,
            CC, C3, CC, CC,
            (long)SS * C3, (long)CC * CC, (long)SS * CC, 1.f / (float)CC);

        // 6) softmax over C (in place)
        softmax_kernel<<<MROWS, 256>>>(att);

        // 7) tmp = gelu(att @ Wp^T + bp)
        hgemm<0,1,1><<<dim3(CC/128, MROWS/128, 1), 256, SMEM_BYTES>>>(
            att, Wp, bp, tmp, CC, CC, CC, CC, 0, 0, 0, 1.f);

        // 8) h = tmp (+ pred for i>0); pred = tmp at i==0
        combine_kernel<<<(unsigned)((n4_h + 255) / 256), 256>>>(
            tmp, pred, h, (i == 0) ? 1 : 0, n4_h);
    }

    // 9) out = h @ fc_out_w^T + fc_out_b
    hgemm<0,1,0><<<dim3(CC/128, MROWS/128, 1), 256, SMEM_BYTES>>>(
        h, fc_out_w, fc_out_b, out, CC, CC, CC, CC, 0, 0, 0, 1.f);

    // 10) out += positional encoding
    pe_add_kernel<<<(unsigned)(((long)MROWS * CC + 255) / 256), 256>>>(out);
}

// round 8
// speedup vs baseline: 2.6741x; 1.2552x over previous
#include <cuda_runtime.h>
#include <cuda_bf16.h>
#include <math.h>
#include <stdint.h>

// Problem constants
#define BB 4
#define SS 2048
#define CC 1024
#define HH 4
#define MROWS (BB*SS)        // 8192
#define C3 (3*CC)            // 3072

// ---------------------------------------------------------------------------
// Scratch (static device globals; no runtime allocation)
// ---------------------------------------------------------------------------
__device__ __align__(128) float g_f32 [MROWS*(long)CC];   // shared fp32 temp
__device__ __align__(128) float g_pred[MROWS*(long)CC];

// bf16 hi/lo planes
__device__ __align__(128) __nv_bfloat16 g_xh [MROWS*(long)CC],  g_xl [MROWS*(long)CC];
__device__ __align__(128) __nv_bfloat16 g_hh [MROWS*(long)CC],  g_hl [MROWS*(long)CC];
__device__ __align__(128) __nv_bfloat16 g_qh [MROWS*(long)C3],  g_ql [MROWS*(long)C3];
__device__ __align__(128) __nv_bfloat16 g_kvh[BB*(long)CC*CC],  g_kvl[BB*(long)CC*CC];
__device__ __align__(128) __nv_bfloat16 g_ah [MROWS*(long)CC],  g_al [MROWS*(long)CC];
__device__ __align__(128) __nv_bfloat16 g_wfih[CC*(long)CC],    g_wfil[CC*(long)CC];
__device__ __align__(128) __nv_bfloat16 g_wqh [HH*(long)C3*CC], g_wql [HH*(long)C3*CC];
__device__ __align__(128) __nv_bfloat16 g_wph [HH*(long)CC*CC], g_wpl [HH*(long)CC*CC];
__device__ __align__(128) __nv_bfloat16 g_wfoh[CC*(long)CC],    g_wfol[CC*(long)CC];

// ---------------------------------------------------------------------------
// Helpers
// ---------------------------------------------------------------------------
__device__ __forceinline__ uint32_t smem_u32(const void* p) {
    uint32_t a;
    asm("{ .reg .u64 t; cvta.to.shared.u64 t, %1; cvt.u32.u64 %0, t; }" : "=r"(a) : "l"(p));
    return a;
}
__device__ __forceinline__ uint16_t b16(float f) {
    __nv_bfloat16 h = __float2bfloat16_rn(f);
    return reinterpret_cast<uint16_t&>(h);
}
__device__ __forceinline__ float fb16(uint16_t u) {
    __nv_bfloat16 h = reinterpret_cast<__nv_bfloat16&>(u);
    return __bfloat162float(h);
}
__device__ __forceinline__ void ldsm4(uint32_t* r, uint32_t addr) {
    asm volatile("ldmatrix.sync.aligned.m8n8.x4.shared.b16 {%0,%1,%2,%3}, [%4];"
                 : "=r"(r[0]), "=r"(r[1]), "=r"(r[2]), "=r"(r[3]) : "r"(addr));
}
__device__ __forceinline__ void ldsm4t(uint32_t* r, uint32_t addr) {
    asm volatile("ldmatrix.sync.aligned.m8n8.x4.trans.shared.b16 {%0,%1,%2,%3}, [%4];"
                 : "=r"(r[0]), "=r"(r[1]), "=r"(r[2]), "=r"(r[3]) : "r"(addr));
}
__device__ __forceinline__ void mma16816(float* c, const uint32_t* a, const uint32_t* b) {
    asm volatile(
        "mma.sync.aligned.m16n8k16.row.col.f32.bf16.bf16.f32 "
        "{%0,%1,%2,%3}, {%4,%5,%6,%7}, {%8,%9}, {%0,%1,%2,%3};"
        : "+f"(c[0]), "+f"(c[1]), "+f"(c[2]), "+f"(c[3])
        : "r"(a[0]), "r"(a[1]), "r"(a[2]), "r"(a[3]), "r"(b[0]), "r"(b[1]));
}
__device__ __forceinline__ void cpa16(uint32_t s, const void* g) {
    asm volatile("cp.async.ca.shared.global [%0], [%1], 16;" :: "r"(s), "l"(g));
}
#define CP_COMMIT() asm volatile("cp.async.commit_group;" ::: "memory")
#define CP_WAIT2()  asm volatile("cp.async.wait_group 2;" ::: "memory")

__device__ __forceinline__ float gelu1(float x) {
    return 0.5f * x * (1.f + erff(x * 0.70710678118654752f));
}
// hi/lo split of 4 floats, packed as 2x uint32 (2 bf16 each)
__device__ __forceinline__ void cvt_hl(float4 v, uint2& h, uint2& l) {
    uint16_t hx = b16(v.x), hy = b16(v.y), hz = b16(v.z), hw = b16(v.w);
    uint16_t lx = b16(v.x - fb16(hx)), ly = b16(v.y - fb16(hy));
    uint16_t lz = b16(v.z - fb16(hz)), lw = b16(v.w - fb16(hw));
    h.x = (uint32_t)hx | ((uint32_t)hy << 16);
    h.y = (uint32_t)hz | ((uint32_t)hw << 16);
    l.x = (uint32_t)lx | ((uint32_t)ly << 16);
    l.y = (uint32_t)lz | ((uint32_t)lw << 16);
}

// ---------------------------------------------------------------------------
// bf16x3-emulated fp32 GEMM, cp.async 4-stage pipeline.
//   C[m,n] = alpha * sum_k op(A)[m,k]*op(B)[k,n] + bias[n]  (+GELU) (+plane out)
//   TR==0: A [m][k] k-contig, B [n][k] k-contig (both via normal ldmatrix)
//   TR==1: A [k][m] m-contig, B [k][n] n-contig (both via ldmatrix.trans)
// CTA 128x128, KT=16, 256 threads, warp tile 64x32, 2 CTAs/SM.
// smem stage = 4 planes (Ah, Al, Bh, Bl); 4 stages.
// ---------------------------------------------------------------------------
#define KT 16
#define LDN 24        // normal plane row stride in bf16 (16 data + 8 pad)
#define LDT 136       // trans  plane row stride in bf16 (128 data + 8 pad)
#define PLB 6144      // plane bytes (normal: 128*48; trans 16*272=4352 fits)
#define STGB (4*PLB)  // 24576
#define NSTG 4
#define SMEM_BYTES (NSTG*STGB)   // 98304

template<int TR, int ACT, int OUT>
__global__ void __launch_bounds__(256, 2)
hgemm(const __nv_bfloat16* __restrict__ Ah_g, const __nv_bfloat16* __restrict__ Al_g,
      const __nv_bfloat16* __restrict__ Bh_g, const __nv_bfloat16* __restrict__ Bl_g,
      const float* __restrict__ bias, float* __restrict__ Cg,
      __nv_bfloat16* __restrict__ Chg, __nv_bfloat16* __restrict__ Clg,
      int K, int lda, int ldb, int ldc,
      long sA, long sB, long sC, float alpha)
{
    extern __shared__ __align__(128) char smem[];
    const uint32_t sbase = smem_u32(smem);

    const int tid  = threadIdx.x;
    const int lane = tid & 31;
    const int wid  = tid >> 5;
    const int m0 = blockIdx.y * 128;
    const int n0 = blockIdx.x * 128;
    const int wm = (wid & 1) * 64;
    const int wn = (wid >> 1) * 32;

    const __nv_bfloat16* Ah = Ah_g + (long)blockIdx.z * sA;
    const __nv_bfloat16* Al = Al_g + (long)blockIdx.z * sA;
    const __nv_bfloat16* Bh = Bh_g + (long)blockIdx.z * sB;
    const __nv_bfloat16* Bl = Bl_g + (long)blockIdx.z * sB;

    float acc[4][4][4];
    #pragma unroll
    for (int i = 0; i < 4; i++)
        #pragma unroll
        for (int j = 0; j < 4; j++)
            #pragma unroll
            for (int e = 0; e < 4; e++) acc[i][j][e] = 0.f;

    // per-thread copy coordinates
    // normal: 128 rows x 2 chunks of 16B (8 bf16)
    const long gAn = (long)(m0 + (tid >> 1)) * lda + (tid & 1) * 8;
    const long gBn = (long)(n0 + (tid >> 1)) * ldb + (tid & 1) * 8;
    const uint32_t sOn = (uint32_t)((tid >> 1) * 48 + (tid & 1) * 16);
    // trans: 16 rows x 16 chunks of 16B
    const long gAt = (long)(tid >> 4) * lda + m0 + (tid & 15) * 8;
    const long gBt = (long)(tid >> 4) * ldb + n0 + (tid & 15) * 8;
    const uint32_t sOt = (uint32_t)((tid >> 4) * 272 + (tid & 15) * 16);

    auto issue_tile = [&](int t) {
        uint32_t sb = sbase + (uint32_t)(t & (NSTG-1)) * STGB;
        const int k0 = t * KT;
        if (TR == 0) {
            cpa16(sb          + sOn, Ah + gAn + k0);
            cpa16(sb +   PLB  + sOn, Al + gAn + k0);
            cpa16(sb + 2*PLB  + sOn, Bh + gBn + k0);
            cpa16(sb + 3*PLB  + sOn, Bl + gBn + k0);
        } else {
            const long ka = (long)k0 * lda;
            const long kb = (long)k0 * ldb;
            cpa16(sb          + sOt, Ah + gAt + ka);
            cpa16(sb +   PLB  + sOt, Al + gAt + ka);
            cpa16(sb + 2*PLB  + sOt, Bh + gBt + kb);
            cpa16(sb + 3*PLB  + sOt, Bl + gBt + kb);
        }
    };

    // ldmatrix lane addressing
    const int arow  = lane & 15;                          // TR0 A
    const int akof  = (lane >> 4) * 8;
    const int brow  = (lane >> 4) * 8 + (lane & 7);       // TR0 B
    const int bkof  = ((lane >> 3) & 1) * 8;
    const int akrow = ((lane >> 4) & 1) * 8 + (lane & 7); // TR1 A
    const int amc   = ((lane >> 3) & 1) * 8;
    const int bkrow = ((lane >> 3) & 1) * 8 + (lane & 7); // TR1 B
    const int bnc   = (lane >> 4) * 8;

    const int nt = K / KT;
    issue_tile(0); CP_COMMIT();
    issue_tile(1); CP_COMMIT();
    issue_tile(2); CP_COMMIT();

    for (int t = 0; t < nt; t++) {
        CP_WAIT2();
        __syncthreads();
        if (t + 3 < nt) issue_tile(t + 3);
        CP_COMMIT();

        const uint32_t sb = sbase + (uint32_t)(t & (NSTG-1)) * STGB;

        uint32_t bh[4][2], bl[4][2];
        #pragma unroll
        for (int np = 0; np < 2; np++) {
            uint32_t off;
            if (TR == 0) off = sb + 2*PLB + (uint32_t)(((wn + np*16 + brow)*LDN + bkof) * 2);
            else         off = sb + 2*PLB + (uint32_t)((bkrow*LDT + wn + np*16 + bnc) * 2);
            uint32_t r[4];
            if (TR == 0) ldsm4(r, off); else ldsm4t(r, off);
            bh[2*np][0] = r[0]; bh[2*np][1] = r[1];
            bh[2*np+1][0] = r[2]; bh[2*np+1][1] = r[3];
            if (TR == 0) ldsm4(r, off + PLB); else ldsm4t(r, off + PLB);
            bl[2*np][0] = r[0]; bl[2*np][1] = r[1];
            bl[2*np+1][0] = r[2]; bl[2*np+1][1] = r[3];
        }
        #pragma unroll
        for (int mt = 0; mt < 4; mt++) {
            uint32_t off;
            if (TR == 0) off = sb + (uint32_t)(((wm + mt*16 + arow)*LDN + akof) * 2);
            else         off = sb + (uint32_t)((akrow*LDT + wm + mt*16 + amc) * 2);
            uint32_t ah[4], al[4];
            if (TR == 0) { ldsm4(ah, off); ldsm4(al, off + PLB); }
            else         { ldsm4t(ah, off); ldsm4t(al, off + PLB); }
            #pragma unroll
            for (int ntl = 0; ntl < 4; ntl++) {
                mma16816(acc[mt][ntl], ah, bh[ntl]);
                mma16816(acc[mt][ntl], ah, bl[ntl]);
                mma16816(acc[mt][ntl], al, bh[ntl]);
            }
        }
    }

    // -------- epilogue --------
    float* C = Cg ? Cg + (long)blockIdx.z * sC : nullptr;
    __nv_bfloat16* Ch = Chg ? Chg + (long)blockIdx.z * sC : nullptr;
    __nv_bfloat16* Cl = Clg ? Clg + (long)blockIdx.z * sC : nullptr;

    const int r  = lane >> 2;
    const int cp = (lane & 3) * 2;
    #pragma unroll
    for (int mt = 0; mt < 4; mt++) {
        #pragma unroll
        for (int ntl = 0; ntl < 4; ntl++) {
            int col = n0 + wn + ntl*8 + cp;
            float b0 = 0.f, b1 = 0.f;
            if (bias) { float2 bb = *(const float2*)(bias + col); b0 = bb.x; b1 = bb.y; }
            float v0 = acc[mt][ntl][0]*alpha + b0;
            float v1 = acc[mt][ntl][1]*alpha + b1;
            float v2 = acc[mt][ntl][2]*alpha + b0;
            float v3 = acc[mt][ntl][3]*alpha + b1;
            if (ACT == 1) { v0 = gelu1(v0); v1 = gelu1(v1); v2 = gelu1(v2); v3 = gelu1(v3); }
            long g0 = (long)(m0 + wm + mt*16 + r) * ldc + col;
            long g1 = g0 + 8L*ldc;
            if (OUT == 0) {
                *(float2*)(C + g0) = make_float2(v0, v1);
                *(float2*)(C + g1) = make_float2(v2, v3);
            } else {
                uint16_t h0 = b16(v0), h1 = b16(v1), h2 = b16(v2), h3 = b16(v3);
                uint16_t l0 = b16(v0 - fb16(h0)), l1 = b16(v1 - fb16(h1));
                uint16_t l2 = b16(v2 - fb16(h2)), l3 = b16(v3 - fb16(h3));
                *(uint32_t*)(Ch + g0) = (uint32_t)h0 | ((uint32_t)h1 << 16);
                *(uint32_t*)(Cl + g0) = (uint32_t)l0 | ((uint32_t)l1 << 16);
                *(uint32_t*)(Ch + g1) = (uint32_t)h2 | ((uint32_t)h3 << 16);
                *(uint32_t*)(Cl + g1) = (uint32_t)l2 | ((uint32_t)l3 << 16);
            }
        }
    }
}

// ---------------------------------------------------------------------------
// Elementwise kernels
// ---------------------------------------------------------------------------
__device__ __forceinline__ float warp_sum(float v) {
    #pragma unroll
    for (int o = 16; o > 0; o >>= 1) v += __shfl_xor_sync(0xffffffffu, v, o);
    return v;
}
__device__ __forceinline__ float warp_max(float v) {
    #pragma unroll
    for (int o = 16; o > 0; o >>= 1) v = fmaxf(v, __shfl_xor_sync(0xffffffffu, v, o));
    return v;
}

// fp32 -> bf16 hi/lo planes (float4 per thread)
__global__ void split_kernel(const float* __restrict__ in,
                             __nv_bfloat16* __restrict__ hi,
                             __nv_bfloat16* __restrict__ lo, long n4)
{
    long i = (long)blockIdx.x * blockDim.x + threadIdx.x;
    if (i >= n4) return;
    float4 v = ((const float4*)in)[i];
    uint2 h, l; cvt_hl(v, h, l);
    ((uint2*)hi)[i] = h;
    ((uint2*)lo)[i] = l;
}

// LayerNorm over C=1024 -> hi/lo planes. One block (256 thr) per row.
__global__ void ln_kernel(const float* __restrict__ in,
                          __nv_bfloat16* __restrict__ oh, __nv_bfloat16* __restrict__ ol,
                          const float* __restrict__ g, const float* __restrict__ b)
{
    long row = blockIdx.x;
    const float4* r4 = (const float4*)(in + row * CC);
    float4 v = r4[threadIdx.x];
    float s  = v.x + v.y + v.z + v.w;
    float ss = v.x*v.x + v.y*v.y + v.z*v.z + v.w*v.w;
    __shared__ float sm[16];
    s = warp_sum(s); ss = warp_sum(ss);
    int w = threadIdx.x >> 5, l = threadIdx.x & 31;
    if (l == 0) { sm[w] = s; sm[8+w] = ss; }
    __syncthreads();
    float tot = 0.f, tots = 0.f;
    #pragma unroll
    for (int i = 0; i < 8; i++) { tot += sm[i]; tots += sm[8+i]; }
    float mu  = tot * (1.f/CC);
    float var = tots * (1.f/CC) - mu*mu;
    float rr  = rsqrtf(var + 1e-5f);
    float4 gv = ((const float4*)g)[threadIdx.x];
    float4 bv = ((const float4*)b)[threadIdx.x];
    float4 o;
    o.x = (v.x - mu)*rr*gv.x + bv.x;
    o.y = (v.y - mu)*rr*gv.y + bv.y;
    o.z = (v.z - mu)*rr*gv.z + bv.z;
    o.w = (v.w - mu)*rr*gv.w + bv.w;
    uint2 hh, ll; cvt_hl(o, hh, ll);
    ((uint2*)(oh + row * CC))[threadIdx.x] = hh;
    ((uint2*)(ol + row * CC))[threadIdx.x] = ll;
}

// Softmax over C=1024: fp32 in -> hi/lo planes out.
__global__ void softmax_kernel(const float* __restrict__ x,
                               __nv_bfloat16* __restrict__ oh, __nv_bfloat16* __restrict__ ol)
{
    long row = blockIdx.x;
    const float4* r4 = (const float4*)(x + row * CC);
    float4 v = r4[threadIdx.x];
    float m = fmaxf(fmaxf(v.x, v.y), fmaxf(v.z, v.w));
    __shared__ float sm[8];
    m = warp_max(m);
    int w = threadIdx.x >> 5, l = threadIdx.x & 31;
    if (l == 0) sm[w] = m;
    __syncthreads();
    float M = sm[0];
    #pragma unroll
    for (int i = 1; i < 8; i++) M = fmaxf(M, sm[i]);
    __syncthreads();
    float4 e;
    e.x = expf(v.x - M); e.y = expf(v.y - M);
    e.z = expf(v.z - M); e.w = expf(v.w - M);
    float s = warp_sum(e.x + e.y + e.z + e.w);
    if (l == 0) sm[w] = s;
    __syncthreads();
    float tot = 0.f;
    #pragma unroll
    for (int i = 0; i < 8; i++) tot += sm[i];
    float inv = 1.f / tot;
    e.x *= inv; e.y *= inv; e.z *= inv; e.w *= inv;
    uint2 hh, ll; cvt_hl(e, hh, ll);
    ((uint2*)(oh + row * CC))[threadIdx.x] = hh;
    ((uint2*)(ol + row * CC))[threadIdx.x] = ll;
}

// h = t (+ pred if !first) -> hi/lo planes; pred captured fp32 on first layer.
__global__ void combine_kernel(const float* __restrict__ t,
                               float* __restrict__ pred,
                               __nv_bfloat16* __restrict__ oh, __nv_bfloat16* __restrict__ ol,
                               int first, long n4)
{
    long i = (long)blockIdx.x * blockDim.x + threadIdx.x;
    if (i >= n4) return;
    float4 v = ((const float4*)t)[i];
    if (first) {
        ((float4*)pred)[i] = v;
    } else {
        float4 p = ((const float4*)pred)[i];
        v.x += p.x; v.y += p.y; v.z += p.z; v.w += p.w;
    }
    uint2 hh, ll; cvt_hl(v, hh, ll);
    ((uint2*)oh)[i] = hh;
    ((uint2*)ol)[i] = ll;
}

__global__ void pe_add_kernel(float* __restrict__ out)
{
    long idx = (long)blockIdx.x * blockDim.x + threadIdx.x;
    if (idx >= (long)MROWS * CC) return;
    int c = (int)(idx & (CC-1));
    int s = (int)((idx >> 10) & (SS-1));
    float inv = exp2f(-0.0194644224310f * (float)c);
    float arg = (float)s * inv;
    out[idx] += (s & 1) ? cosf(arg) : sinf(arg);
}

// ---------------------------------------------------------------------------
// Host orchestration (graph-capturable)
// ---------------------------------------------------------------------------
extern "C" void kernel_launch(void* const* d_in, const int* in_sizes, int n_in,
                              void* d_out, int out_size)
{
    const float* x        = (const float*)d_in[0];
    const float* fc_in_w  = (const float*)d_in[1];
    const float* fc_in_b  = (const float*)d_in[2];
    const float* ln_g     = (const float*)d_in[3];
    const float* ln_b     = (const float*)d_in[4];
    const float* qkv_w    = (const float*)d_in[5];
    const float* qkv_b    = (const float*)d_in[6];
    const float* proj_w   = (const float*)d_in[7];
    const float* proj_b   = (const float*)d_in[8];
    const float* fc_out_w = (const float*)d_in[9];
    const float* fc_out_b = (const float*)d_in[10];
    float* out = (float*)d_out;

    float *f32, *pred;
    __nv_bfloat16 *xh, *xl, *hh, *hl, *qh, *ql, *kvh, *kvl, *ah, *al;
    __nv_bfloat16 *wfih, *wfil, *wqh, *wql, *wph, *wpl, *wfoh, *wfol;
    cudaGetSymbolAddress((void**)&f32,  g_f32);
    cudaGetSymbolAddress((void**)&pred, g_pred);
    cudaGetSymbolAddress((void**)&xh,   g_xh);   cudaGetSymbolAddress((void**)&xl,   g_xl);
    cudaGetSymbolAddress((void**)&hh,   g_hh);   cudaGetSymbolAddress((void**)&hl,   g_hl);
    cudaGetSymbolAddress((void**)&qh,   g_qh);   cudaGetSymbolAddress((void**)&ql,   g_ql);
    cudaGetSymbolAddress((void**)&kvh,  g_kvh);  cudaGetSymbolAddress((void**)&kvl,  g_kvl);
    cudaGetSymbolAddress((void**)&ah,   g_ah);   cudaGetSymbolAddress((void**)&al,   g_al);
    cudaGetSymbolAddress((void**)&wfih, g_wfih); cudaGetSymbolAddress((void**)&wfil, g_wfil);
    cudaGetSymbolAddress((void**)&wqh,  g_wqh);  cudaGetSymbolAddress((void**)&wql,  g_wql);
    cudaGetSymbolAddress((void**)&wph,  g_wph);  cudaGetSymbolAddress((void**)&wpl,  g_wpl);
    cudaGetSymbolAddress((void**)&wfoh, g_wfoh); cudaGetSymbolAddress((void**)&wfol, g_wfol);

    cudaFuncSetAttribute(hgemm<0,0,0>, cudaFuncAttributeMaxDynamicSharedMemorySize, SMEM_BYTES);
    cudaFuncSetAttribute(hgemm<0,1,1>, cudaFuncAttributeMaxDynamicSharedMemorySize, SMEM_BYTES);
    cudaFuncSetAttribute(hgemm<0,1,0>, cudaFuncAttributeMaxDynamicSharedMemorySize, SMEM_BYTES);
    cudaFuncSetAttribute(hgemm<1,0,1>, cudaFuncAttributeMaxDynamicSharedMemorySize, SMEM_BYTES);

    const long n4_h = (long)MROWS * CC / 4;

    auto split = [&](const float* src, __nv_bfloat16* h_, __nv_bfloat16* l_, long elems) {
        long n4 = elems / 4;
        split_kernel<<<(unsigned)((n4 + 255) / 256), 256>>>(src, h_, l_, n4);
    };

    // 0) split inputs/weights into bf16 hi/lo planes
    split(x,        xh,   xl,   (long)MROWS * CC);
    split(fc_in_w,  wfih, wfil, (long)CC * CC);
    split(qkv_w,    wqh,  wql,  (long)HH * C3 * CC);
    split(proj_w,   wph,  wpl,  (long)HH * CC * CC);
    split(fc_out_w, wfoh, wfol, (long)CC * CC);

    // 1) f32 = x @ fc_in_w^T + fc_in_b
    hgemm<0,0,0><<<dim3(CC/128, MROWS/128, 1), 256, SMEM_BYTES>>>(
        xh, xl, wfih, wfil, fc_in_b, f32, nullptr, nullptr,
        CC, CC, CC, CC, 0, 0, 0, 1.f);

    // 2) h planes = LN(f32)
    ln_kernel<<<MROWS, 256>>>(f32, hh, hl, ln_g, ln_b);

    for (int i = 0; i < HH; i++) {
        const __nv_bfloat16* Wqh = wqh + (long)i * C3 * CC;
        const __nv_bfloat16* Wql = wql + (long)i * C3 * CC;
        const float*         bq  = qkv_b + (long)i * C3;
        const __nv_bfloat16* Wph = wph + (long)i * CC * CC;
        const __nv_bfloat16* Wpl = wpl + (long)i * CC * CC;
        const float*         bp  = proj_b + (long)i * CC;

        // 3) qkv planes = gelu(h @ Wq^T + bq)  [8192 x 3072]
        hgemm<0,1,1><<<dim3(C3/128, MROWS/128, 1), 256, SMEM_BYTES>>>(
            hh, hl, Wqh, Wql, bq, nullptr, qh, ql,
            CC, CC, CC, C3, 0, 0, 0, 1.f);

        // 4) kvT[b][cv][ck] = sum_s v[s][cv]*k[s][ck]  (TR: both operands [s][c])
        hgemm<1,0,1><<<dim3(CC/128, CC/128, BB), 256, SMEM_BYTES>>>(
            qh + 2*CC, ql + 2*CC, qh + CC, ql + CC, nullptr, nullptr, kvh, kvl,
            SS, C3, C3, CC,
            (long)SS * C3, (long)SS * C3, (long)CC * CC, 1.f);

        // 5) f32[b] = (q[b] @ kvT[b]^T) / C   [S x C], K = C
        hgemm<0,0,0><<<dim3(CC/128, SS/128, BB), 256, SMEM_BYTES>>>(
            qh, ql, kvh, kvl, nullptr, f32, nullptr, nullptr,
            CC, C3, CC, CC,
            (long)SS * C3, (long)CC * CC, (long)SS * CC, 1.f / (float)CC);

        // 6) att planes = softmax(f32)
        softmax_kernel<<<MROWS, 256>>>(f32, ah, al);

        // 7) f32 = gelu(att @ Wp^T + bp)
        hgemm<0,1,0><<<dim3(CC/128, MROWS/128, 1), 256, SMEM_BYTES>>>(
            ah, al, Wph, Wpl, bp, f32, nullptr, nullptr,
            CC, CC, CC, CC, 0, 0, 0, 1.f);

        // 8) h planes = f32 (+ pred for i>0); pred = f32 at i==0
        combine_kernel<<<(unsigned)((n4_h + 255) / 256), 256>>>(
            f32, pred, hh, hl, (i == 0) ? 1 : 0, n4_h);
    }

    // 9) out = h @ fc_out_w^T + fc_out_b
    hgemm<0,0,0><<<dim3(CC/128, MROWS/128, 1), 256, SMEM_BYTES>>>(
        hh, hl, wfoh, wfol, fc_out_b, out, nullptr, nullptr,
        CC, CC, CC, CC, 0, 0, 0, 1.f);

    // 10) out += positional encoding
    pe_add_kernel<<<(unsigned)(((long)MROWS * CC + 255) / 256), 256>>>(out);
}